// round 1
// baseline (speedup 1.0000x reference)
#include <cuda_runtime.h>
#include <math.h>

// Problem constants
#define B_ 4
#define T_ 2048
#define C_ 1024
#define H_ 16
#define D_ 64
#define BT_ (B_ * T_)           // 8192

// Scratch (static device globals; allocation-free per harness rules)
__device__ float g_q[B_ * H_ * T_ * D_];    // [B,H,T,D]
__device__ float g_k[B_ * H_ * T_ * D_];
__device__ float g_v[B_ * H_ * T_ * D_];
__device__ float g_att[B_ * T_ * C_];       // [B,T,H*D] (concat heads)

// ---------------------------------------------------------------------------
// Kernel 1: QKV projection.  Y = X @ W  with X [8192,1024], W per head [C,D].
// Combined N = 3 * H * D = 3072.  Tile: BM=128, BN=64 (= one head), BK=16.
// 256 threads, each computes 8x4.
// ---------------------------------------------------------------------------
__global__ __launch_bounds__(256) void qkv_kernel(
    const float* __restrict__ x,
    const float* __restrict__ Wq,
    const float* __restrict__ Wk,
    const float* __restrict__ Wv)
{
    __shared__ float As[128][17];   // [m][k], pad to kill bank conflicts
    __shared__ float Bs[16][65];    // [k][n]

    const int mt = blockIdx.x;           // 0..63
    const int nt = blockIdx.y;           // 0..47
    const int which = nt >> 4;           // 0=q 1=k 2=v
    const int h = nt & 15;

    const float* W = (which == 0 ? Wq : (which == 1 ? Wk : Wv)) + (size_t)h * C_ * D_;
    float* outb = (which == 0 ? g_q : (which == 1 ? g_k : g_v));

    const int tid = threadIdx.x;
    const int tx = tid & 15;             // 0..15 -> n groups of 4
    const int ty = tid >> 4;             // 0..15 -> m groups of 8
    const int m0 = mt * 128;

    float acc[8][4];
    #pragma unroll
    for (int i = 0; i < 8; i++)
        #pragma unroll
        for (int j = 0; j < 4; j++) acc[i][j] = 0.0f;

    for (int k0 = 0; k0 < C_; k0 += 16) {
        // load A tile: 128x16 = 2048 elems, 8 per thread
        #pragma unroll
        for (int l = 0; l < 8; l++) {
            int idx = tid + l * 256;
            int i = idx >> 4, j = idx & 15;
            As[i][j] = x[(size_t)(m0 + i) * C_ + k0 + j];
        }
        // load B tile: 16x64 = 1024 elems, 4 per thread
        #pragma unroll
        for (int l = 0; l < 4; l++) {
            int idx = tid + l * 256;
            int r = idx >> 6, cc = idx & 63;
            Bs[r][cc] = W[(size_t)(k0 + r) * D_ + cc];
        }
        __syncthreads();

        #pragma unroll
        for (int kk = 0; kk < 16; kk++) {
            float a[8], bb[4];
            #pragma unroll
            for (int i = 0; i < 8; i++) a[i] = As[ty * 8 + i][kk];
            #pragma unroll
            for (int j = 0; j < 4; j++) bb[j] = Bs[kk][tx * 4 + j];
            #pragma unroll
            for (int i = 0; i < 8; i++)
                #pragma unroll
                for (int j = 0; j < 4; j++) acc[i][j] += a[i] * bb[j];
        }
        __syncthreads();
    }

    // write out: [B,H,T,D] layout
    #pragma unroll
    for (int i = 0; i < 8; i++) {
        int m = m0 + ty * 8 + i;
        int b = m >> 11;             // /T_
        int t = m & (T_ - 1);
        float* dst = outb + (((size_t)(b * H_ + h)) * T_ + t) * D_;
        #pragma unroll
        for (int j = 0; j < 4; j++) dst[tx * 4 + j] = acc[i][j];
    }
}

// ---------------------------------------------------------------------------
// Kernel 2: causal flash attention per (b,h).  BQ=64, BS=64.
// grid (T/64, B*H), 256 threads, 4x4 micro-tiles.
// ---------------------------------------------------------------------------
struct AttnSmem {
    float Qs[64][65];
    float Ks[64][65];
    float Vs[64][65];
    float Ps[64][65];
    float row_m[64];
    float row_l[64];
    float row_alpha[64];
    float red[64][4];
};
#define ATTN_SMEM_BYTES sizeof(AttnSmem)

__global__ __launch_bounds__(256) void attn_kernel()
{
    extern __shared__ char smem_raw[];
    AttnSmem* sm = reinterpret_cast<AttnSmem*>(smem_raw);

    const int tid = threadIdx.x;
    const int tx = tid & 15;
    const int ty = tid >> 4;
    const int qb = blockIdx.x;       // query block 0..31
    const int bh = blockIdx.y;       // 0..63

    const float* qp = g_q + (size_t)bh * T_ * D_;
    const float* kp = g_k + (size_t)bh * T_ * D_;
    const float* vp = g_v + (size_t)bh * T_ * D_;

    // load Q tile (pre-scaled by 1/sqrt(D) = 0.125)
    for (int idx = tid; idx < 64 * 64; idx += 256) {
        int r = idx >> 6, c = idx & 63;
        sm->Qs[r][c] = qp[(size_t)(qb * 64 + r) * D_ + c] * 0.125f;
    }
    if (tid < 64) { sm->row_m[tid] = -INFINITY; sm->row_l[tid] = 0.0f; }

    float acc[4][4];
    #pragma unroll
    for (int i = 0; i < 4; i++)
        #pragma unroll
        for (int j = 0; j < 4; j++) acc[i][j] = 0.0f;

    for (int sb = 0; sb <= qb; sb++) {
        __syncthreads();   // protect Ks/Vs/Ps reuse from previous iteration
        for (int idx = tid; idx < 64 * 64; idx += 256) {
            int r = idx >> 6, c = idx & 63;
            sm->Ks[r][c] = kp[(size_t)(sb * 64 + r) * D_ + c];
            sm->Vs[r][c] = vp[(size_t)(sb * 64 + r) * D_ + c];
        }
        __syncthreads();

        // S = Q @ K^T  (64x64), 4x4 per thread
        float s[4][4];
        #pragma unroll
        for (int i = 0; i < 4; i++)
            #pragma unroll
            for (int j = 0; j < 4; j++) s[i][j] = 0.0f;

        #pragma unroll 8
        for (int kk = 0; kk < 64; kk++) {
            float a[4], bb[4];
            #pragma unroll
            for (int i = 0; i < 4; i++) a[i] = sm->Qs[ty * 4 + i][kk];
            #pragma unroll
            for (int j = 0; j < 4; j++) bb[j] = sm->Ks[tx * 4 + j][kk];
            #pragma unroll
            for (int i = 0; i < 4; i++)
                #pragma unroll
                for (int j = 0; j < 4; j++) s[i][j] += a[i] * bb[j];
        }

        // mask (diagonal block) + store S into Ps
        const bool diag = (sb == qb);
        #pragma unroll
        for (int i = 0; i < 4; i++) {
            int m = ty * 4 + i;
            #pragma unroll
            for (int j = 0; j < 4; j++) {
                int sc = tx * 4 + j;
                float v = s[i][j];
                if (diag && sc > m) v = -INFINITY;
                sm->Ps[m][sc] = v;
            }
        }
        __syncthreads();

        // phase A: partial row max (4 threads per row, 16 cols each)
        {
            int m = tid >> 2, q4 = tid & 3;
            float pm = -INFINITY;
            int c0 = q4 * 16;
            #pragma unroll
            for (int c = 0; c < 16; c++) pm = fmaxf(pm, sm->Ps[m][c0 + c]);
            sm->red[m][q4] = pm;
        }
        __syncthreads();

        // phase B: new max, alpha
        if (tid < 64) {
            int m = tid;
            float mnew = fmaxf(fmaxf(sm->red[m][0], sm->red[m][1]),
                               fmaxf(sm->red[m][2], sm->red[m][3]));
            mnew = fmaxf(mnew, sm->row_m[m]);
            sm->row_alpha[m] = __expf(sm->row_m[m] - mnew);
            sm->row_m[m] = mnew;
        }
        __syncthreads();

        // phase C: exponentiate + partial row sums
        {
            int m = tid >> 2, q4 = tid & 3;
            float mnew = sm->row_m[m];
            float ls = 0.0f;
            int c0 = q4 * 16;
            #pragma unroll
            for (int c = 0; c < 16; c++) {
                float p = __expf(sm->Ps[m][c0 + c] - mnew);
                sm->Ps[m][c0 + c] = p;
                ls += p;
            }
            sm->red[m][q4] = ls;
        }
        __syncthreads();

        // phase D: update row sums
        if (tid < 64) {
            int m = tid;
            sm->row_l[m] = sm->row_l[m] * sm->row_alpha[m] +
                           (sm->red[m][0] + sm->red[m][1] + sm->red[m][2] + sm->red[m][3]);
        }

        // rescale O accumulators
        #pragma unroll
        for (int i = 0; i < 4; i++) {
            float al = sm->row_alpha[ty * 4 + i];
            #pragma unroll
            for (int j = 0; j < 4; j++) acc[i][j] *= al;
        }

        // O += P @ V   (Ps already synced by phase-C barrier)
        #pragma unroll 8
        for (int kk = 0; kk < 64; kk++) {
            float a[4], bb[4];
            #pragma unroll
            for (int i = 0; i < 4; i++) a[i] = sm->Ps[ty * 4 + i][kk];
            #pragma unroll
            for (int j = 0; j < 4; j++) bb[j] = sm->Vs[kk][tx * 4 + j];
            #pragma unroll
            for (int i = 0; i < 4; i++)
                #pragma unroll
                for (int j = 0; j < 4; j++) acc[i][j] += a[i] * bb[j];
        }
    }
    __syncthreads();   // make phase-D row_l visible

    const int b = bh >> 4, h = bh & 15;
    #pragma unroll
    for (int i = 0; i < 4; i++) {
        int m = ty * 4 + i;
        float inv = 1.0f / sm->row_l[m];
        int tq = qb * 64 + m;
        float* dst = g_att + ((size_t)(b * T_ + tq)) * C_ + h * D_;
        #pragma unroll
        for (int j = 0; j < 4; j++) dst[tx * 4 + j] = acc[i][j] * inv;
    }
}

// ---------------------------------------------------------------------------
// Kernel 3: output projection.  out = g_att @ Wo + bo.
// [8192,1024] @ [1024,1024].  BM=128, BN=64, BK=16, 8x4 per thread.
// ---------------------------------------------------------------------------
__global__ __launch_bounds__(256) void proj_kernel(
    float* __restrict__ out,
    const float* __restrict__ Wo,
    const float* __restrict__ bo)
{
    __shared__ float As[128][17];
    __shared__ float Bs[16][65];

    const int mt = blockIdx.x;   // 0..63
    const int nt = blockIdx.y;   // 0..15
    const int tid = threadIdx.x;
    const int tx = tid & 15;
    const int ty = tid >> 4;
    const int m0 = mt * 128;
    const int n0 = nt * 64;

    float acc[8][4];
    #pragma unroll
    for (int i = 0; i < 8; i++)
        #pragma unroll
        for (int j = 0; j < 4; j++) acc[i][j] = 0.0f;

    for (int k0 = 0; k0 < C_; k0 += 16) {
        #pragma unroll
        for (int l = 0; l < 8; l++) {
            int idx = tid + l * 256;
            int i = idx >> 4, j = idx & 15;
            As[i][j] = g_att[(size_t)(m0 + i) * C_ + k0 + j];
        }
        #pragma unroll
        for (int l = 0; l < 4; l++) {
            int idx = tid + l * 256;
            int r = idx >> 6, cc = idx & 63;
            Bs[r][cc] = Wo[(size_t)(k0 + r) * C_ + n0 + cc];
        }
        __syncthreads();

        #pragma unroll
        for (int kk = 0; kk < 16; kk++) {
            float a[8], bb[4];
            #pragma unroll
            for (int i = 0; i < 8; i++) a[i] = As[ty * 8 + i][kk];
            #pragma unroll
            for (int j = 0; j < 4; j++) bb[j] = Bs[kk][tx * 4 + j];
            #pragma unroll
            for (int i = 0; i < 8; i++)
                #pragma unroll
                for (int j = 0; j < 4; j++) acc[i][j] += a[i] * bb[j];
        }
        __syncthreads();
    }

    #pragma unroll
    for (int i = 0; i < 8; i++) {
        int m = m0 + ty * 8 + i;
        #pragma unroll
        for (int j = 0; j < 4; j++) {
            int n = n0 + tx * 4 + j;
            out[(size_t)m * C_ + n] = acc[i][j] + bo[n];
        }
    }
}

// ---------------------------------------------------------------------------
extern "C" void kernel_launch(void* const* d_in, const int* in_sizes, int n_in,
                              void* d_out, int out_size)
{
    const float* x  = (const float*)d_in[0];
    const float* Wq = (const float*)d_in[1];
    const float* Wk = (const float*)d_in[2];
    const float* Wv = (const float*)d_in[3];
    const float* Wo = (const float*)d_in[4];
    const float* bo = (const float*)d_in[5];
    float* out = (float*)d_out;

    cudaFuncSetAttribute(attn_kernel, cudaFuncAttributeMaxDynamicSharedMemorySize,
                         (int)ATTN_SMEM_BYTES);

    qkv_kernel<<<dim3(BT_ / 128, 48), 256>>>(x, Wq, Wk, Wv);
    attn_kernel<<<dim3(T_ / 64, B_ * H_), 256, ATTN_SMEM_BYTES>>>();
    proj_kernel<<<dim3(BT_ / 128, C_ / 64), 256>>>(out, Wo, bo);
}

// round 3
// speedup vs baseline: 2.8531x; 2.8531x over previous
#include <cuda_runtime.h>
#include <math.h>
#include <cstdint>

// Problem constants
#define B_ 4
#define T_ 2048
#define C_ 1024
#define H_ 16
#define D_ 64
#define BT_ (B_ * T_)           // 8192

// Scratch (static device globals; allocation-free per harness rules)
__device__ float g_q[B_ * H_ * T_ * D_];    // [B,H,T,D]
__device__ float g_k[B_ * H_ * T_ * D_];
__device__ float g_v[B_ * H_ * T_ * D_];
__device__ float g_att[B_ * T_ * C_];       // [B,T,H*D] (concat heads)
__device__ float g_wt[3 * C_ * C_];         // transposed qkv weights, K-major [n=3072][k=1024]
__device__ float g_wot[C_ * C_];            // transposed Wo, K-major [n=1024][k=1024]

// ===========================================================================
// Helpers
// ===========================================================================
__device__ __forceinline__ float to_tf32(float x) {
    uint32_t r;
    asm("cvt.rna.tf32.f32 %0, %1;" : "=r"(r) : "f"(x));
    return __uint_as_float(r);
}

__device__ __forceinline__ void mma_tf32(float* c, const uint32_t* a, const uint32_t* b) {
    asm volatile(
        "mma.sync.aligned.m16n8k8.row.col.f32.tf32.tf32.f32 "
        "{%0,%1,%2,%3}, {%4,%5,%6,%7}, {%8,%9}, {%0,%1,%2,%3};\n"
        : "+f"(c[0]), "+f"(c[1]), "+f"(c[2]), "+f"(c[3])
        : "r"(a[0]), "r"(a[1]), "r"(a[2]), "r"(a[3]),
          "r"(b[0]), "r"(b[1]));
}

// SMEM tile geometry: 128 rows x 32 cols, row stride 36 floats (conflict-free
// for mma fragment access pattern: bank = (4*row + col) % 32, all distinct).
#define TROW 36
#define TILE_F (128 * TROW)         // floats per matrix tile  (4608)
#define BUF_F  (2 * TILE_F)         // A + B per buffer        (9216)
#define GEMM_SMEM_BYTES (2 * BUF_F * 4)   // double buffered   (73728)

// ===========================================================================
// Core tf32 mma mainloop: computes C[128,128] = A[128,1024] @ B[128,1024]^T
// A0 row-major [128 x C_] slice, B0 K-major [128 x C_] slice (i.e. B^T rows).
// Accumulators returned in c[4][4][4] (mf, nf, reg).
// ===========================================================================
__device__ __forceinline__ void gemm_mainloop_mma(
    const float* __restrict__ A0, const float* __restrict__ B0,
    float* __restrict__ smf, float c[4][4][4])
{
    const int tid  = threadIdx.x;
    const int lane = tid & 31;
    const int wid  = tid >> 5;
    const int wm = (wid & 1) * 64;       // warp m offset
    const int wn = (wid >> 1) * 32;      // warp n offset
    const int qr = lane >> 2;            // 0..7
    const int qc = lane & 3;             // 0..3

    const int pc4 = tid & 7;             // float4 column within 32-wide tile
    const int pr  = tid >> 3;            // 0..31 (row group base)

    #pragma unroll
    for (int mf = 0; mf < 4; mf++)
        #pragma unroll
        for (int nf = 0; nf < 4; nf++)
            #pragma unroll
            for (int r = 0; r < 4; r++) c[mf][nf][r] = 0.0f;

    float4 pa[4], pb[4];

    // prologue: load chunk 0
    #pragma unroll
    for (int l = 0; l < 4; l++) {
        pa[l] = *(const float4*)(A0 + (size_t)(pr + l * 32) * C_ + pc4 * 4);
        pb[l] = *(const float4*)(B0 + (size_t)(pr + l * 32) * C_ + pc4 * 4);
    }
    {
        float* sA = smf;            // buf 0
        float* sB = smf + TILE_F;
        #pragma unroll
        for (int l = 0; l < 4; l++) {
            float4 va = pa[l];
            va.x = to_tf32(va.x); va.y = to_tf32(va.y);
            va.z = to_tf32(va.z); va.w = to_tf32(va.w);
            *(float4*)(sA + (pr + l * 32) * TROW + pc4 * 4) = va;
            float4 vb = pb[l];
            vb.x = to_tf32(vb.x); vb.y = to_tf32(vb.y);
            vb.z = to_tf32(vb.z); vb.w = to_tf32(vb.w);
            *(float4*)(sB + (pr + l * 32) * TROW + pc4 * 4) = vb;
        }
    }
    __syncthreads();

    for (int kc = 0; kc < 32; kc++) {
        const int buf = kc & 1;
        float* sA = smf + buf * BUF_F;
        float* sB = sA + TILE_F;

        // prefetch next chunk into registers (LDG latency hidden under mma)
        if (kc < 31) {
            const float* An = A0 + (kc + 1) * 32;
            const float* Bn = B0 + (kc + 1) * 32;
            #pragma unroll
            for (int l = 0; l < 4; l++) {
                pa[l] = *(const float4*)(An + (size_t)(pr + l * 32) * C_ + pc4 * 4);
                pb[l] = *(const float4*)(Bn + (size_t)(pr + l * 32) * C_ + pc4 * 4);
            }
        }

        // compute on current buffer: 4 k-steps of 8
        #pragma unroll
        for (int ks = 0; ks < 4; ks++) {
            const int k0 = ks * 8;
            uint32_t a[4][4];
            #pragma unroll
            for (int mf = 0; mf < 4; mf++) {
                const float* ap = sA + (wm + mf * 16 + qr) * TROW + k0 + qc;
                a[mf][0] = __float_as_uint(ap[0]);
                a[mf][1] = __float_as_uint(ap[8 * TROW]);
                a[mf][2] = __float_as_uint(ap[4]);
                a[mf][3] = __float_as_uint(ap[8 * TROW + 4]);
            }
            uint32_t b[4][2];
            #pragma unroll
            for (int nf = 0; nf < 4; nf++) {
                const float* bp = sB + (wn + nf * 8 + qr) * TROW + k0 + qc;
                b[nf][0] = __float_as_uint(bp[0]);
                b[nf][1] = __float_as_uint(bp[4]);
            }
            #pragma unroll
            for (int mf = 0; mf < 4; mf++)
                #pragma unroll
                for (int nf = 0; nf < 4; nf++)
                    mma_tf32(c[mf][nf], a[mf], b[nf]);
        }

        // store prefetched chunk into the other buffer
        if (kc < 31) {
            float* dA = smf + (buf ^ 1) * BUF_F;
            float* dB = dA + TILE_F;
            #pragma unroll
            for (int l = 0; l < 4; l++) {
                float4 va = pa[l];
                va.x = to_tf32(va.x); va.y = to_tf32(va.y);
                va.z = to_tf32(va.z); va.w = to_tf32(va.w);
                *(float4*)(dA + (pr + l * 32) * TROW + pc4 * 4) = va;
                float4 vb = pb[l];
                vb.x = to_tf32(vb.x); vb.y = to_tf32(vb.y);
                vb.z = to_tf32(vb.z); vb.w = to_tf32(vb.w);
                *(float4*)(dB + (pr + l * 32) * TROW + pc4 * 4) = vb;
            }
        }
        __syncthreads();
    }
}

// ===========================================================================
// Weight transpose kernels (N-major -> K-major)
// ===========================================================================
__global__ __launch_bounds__(256) void transpose_qkv_w(
    const float* __restrict__ Wq, const float* __restrict__ Wk,
    const float* __restrict__ Wv)
{
    __shared__ float tile[32][33];
    const int z = blockIdx.z;               // 0..47
    const int which = z >> 4, h = z & 15;
    const float* W = (which == 0 ? Wq : (which == 1 ? Wk : Wv)) + (size_t)h * C_ * D_;
    const int c0 = blockIdx.x * 32;         // C dim (1024)
    const int d0 = blockIdx.y * 32;         // D dim (64)
    const int tx = threadIdx.x & 31, ty = threadIdx.x >> 5;

    #pragma unroll
    for (int i = 0; i < 4; i++)
        tile[ty + i * 8][tx] = W[(size_t)(c0 + ty + i * 8) * D_ + d0 + tx];
    __syncthreads();
    const int nbase = which * 1024 + h * 64 + d0;
    #pragma unroll
    for (int i = 0; i < 4; i++)
        g_wt[(size_t)(nbase + ty + i * 8) * C_ + c0 + tx] = tile[tx][ty + i * 8];
}

__global__ __launch_bounds__(256) void transpose_wo(const float* __restrict__ Wo)
{
    __shared__ float tile[32][33];
    const int c0 = blockIdx.x * 32;
    const int n0 = blockIdx.y * 32;
    const int tx = threadIdx.x & 31, ty = threadIdx.x >> 5;
    #pragma unroll
    for (int i = 0; i < 4; i++)
        tile[ty + i * 8][tx] = Wo[(size_t)(c0 + ty + i * 8) * C_ + n0 + tx];
    __syncthreads();
    #pragma unroll
    for (int i = 0; i < 4; i++)
        g_wot[(size_t)(n0 + ty + i * 8) * C_ + c0 + tx] = tile[tx][ty + i * 8];
}

// ===========================================================================
// Kernel 1: QKV projection via mma.sync tf32.  grid (64, 24), 256 threads.
// ===========================================================================
extern __shared__ __align__(16) float dyn_smf[];

__global__ __launch_bounds__(256) void qkv_tc(const float* __restrict__ x)
{
    const int mt = blockIdx.x, nt = blockIdx.y;
    const float* A0 = x + (size_t)mt * 128 * C_;
    const float* B0 = g_wt + (size_t)nt * 128 * C_;

    float c[4][4][4];
    gemm_mainloop_mma(A0, B0, dyn_smf, c);

    const int tid  = threadIdx.x;
    const int lane = tid & 31;
    const int wid  = tid >> 5;
    const int wm = (wid & 1) * 64;
    const int wn = (wid >> 1) * 32;
    const int qr = lane >> 2;
    const int qc = lane & 3;

    #pragma unroll
    for (int mf = 0; mf < 4; mf++) {
        #pragma unroll
        for (int half = 0; half < 2; half++) {
            const int m = mt * 128 + wm + mf * 16 + qr + half * 8;
            const int b = m >> 11, t = m & (T_ - 1);
            #pragma unroll
            for (int nf = 0; nf < 4; nf++) {
                const int n = nt * 128 + wn + nf * 8 + qc * 2;
                const int which = n >> 10;
                const int hh = (n >> 6) & 15;
                const int d = n & 63;
                float* op = (which == 0 ? g_q : (which == 1 ? g_k : g_v))
                            + ((size_t)(b * H_ + hh) * T_ + t) * D_ + d;
                float2 v = half == 0
                    ? make_float2(c[mf][nf][0], c[mf][nf][1])
                    : make_float2(c[mf][nf][2], c[mf][nf][3]);
                *(float2*)op = v;
            }
        }
    }
}

// ===========================================================================
// Kernel 3: output projection via mma.sync tf32 + bias.  grid (64, 8).
// ===========================================================================
__global__ __launch_bounds__(256) void proj_tc(float* __restrict__ out,
                                               const float* __restrict__ bo)
{
    const int mt = blockIdx.x, nt = blockIdx.y;
    const float* A0 = g_att + (size_t)mt * 128 * C_;
    const float* B0 = g_wot + (size_t)nt * 128 * C_;

    float c[4][4][4];
    gemm_mainloop_mma(A0, B0, dyn_smf, c);

    const int tid  = threadIdx.x;
    const int lane = tid & 31;
    const int wid  = tid >> 5;
    const int wm = (wid & 1) * 64;
    const int wn = (wid >> 1) * 32;
    const int qr = lane >> 2;
    const int qc = lane & 3;

    #pragma unroll
    for (int mf = 0; mf < 4; mf++) {
        #pragma unroll
        for (int half = 0; half < 2; half++) {
            const int m = mt * 128 + wm + mf * 16 + qr + half * 8;
            #pragma unroll
            for (int nf = 0; nf < 4; nf++) {
                const int n = nt * 128 + wn + nf * 8 + qc * 2;
                float2 bv = *(const float2*)(bo + n);
                float2 v = half == 0
                    ? make_float2(c[mf][nf][0] + bv.x, c[mf][nf][1] + bv.y)
                    : make_float2(c[mf][nf][2] + bv.x, c[mf][nf][3] + bv.y);
                *(float2*)(out + (size_t)m * C_ + n) = v;
            }
        }
    }
}

// ===========================================================================
// Kernel 2: causal flash attention (scalar, unchanged — known good).
// ===========================================================================
struct AttnSmem {
    float Qs[64][65];
    float Ks[64][65];
    float Vs[64][65];
    float Ps[64][65];
    float row_m[64];
    float row_l[64];
    float row_alpha[64];
    float red[64][4];
};
#define ATTN_SMEM_BYTES sizeof(AttnSmem)

__global__ __launch_bounds__(256) void attn_kernel()
{
    extern __shared__ char smem_raw[];
    AttnSmem* sm = reinterpret_cast<AttnSmem*>(smem_raw);

    const int tid = threadIdx.x;
    const int tx = tid & 15;
    const int ty = tid >> 4;
    const int qb = blockIdx.x;
    const int bh = blockIdx.y;

    const float* qp = g_q + (size_t)bh * T_ * D_;
    const float* kp = g_k + (size_t)bh * T_ * D_;
    const float* vp = g_v + (size_t)bh * T_ * D_;

    for (int idx = tid; idx < 64 * 64; idx += 256) {
        int r = idx >> 6, c = idx & 63;
        sm->Qs[r][c] = qp[(size_t)(qb * 64 + r) * D_ + c] * 0.125f;
    }
    if (tid < 64) { sm->row_m[tid] = -INFINITY; sm->row_l[tid] = 0.0f; }

    float acc[4][4];
    #pragma unroll
    for (int i = 0; i < 4; i++)
        #pragma unroll
        for (int j = 0; j < 4; j++) acc[i][j] = 0.0f;

    for (int sb = 0; sb <= qb; sb++) {
        __syncthreads();
        for (int idx = tid; idx < 64 * 64; idx += 256) {
            int r = idx >> 6, c = idx & 63;
            sm->Ks[r][c] = kp[(size_t)(sb * 64 + r) * D_ + c];
            sm->Vs[r][c] = vp[(size_t)(sb * 64 + r) * D_ + c];
        }
        __syncthreads();

        float s[4][4];
        #pragma unroll
        for (int i = 0; i < 4; i++)
            #pragma unroll
            for (int j = 0; j < 4; j++) s[i][j] = 0.0f;

        #pragma unroll 8
        for (int kk = 0; kk < 64; kk++) {
            float a[4], bb[4];
            #pragma unroll
            for (int i = 0; i < 4; i++) a[i] = sm->Qs[ty * 4 + i][kk];
            #pragma unroll
            for (int j = 0; j < 4; j++) bb[j] = sm->Ks[tx * 4 + j][kk];
            #pragma unroll
            for (int i = 0; i < 4; i++)
                #pragma unroll
                for (int j = 0; j < 4; j++) s[i][j] += a[i] * bb[j];
        }

        const bool diag = (sb == qb);
        #pragma unroll
        for (int i = 0; i < 4; i++) {
            int m = ty * 4 + i;
            #pragma unroll
            for (int j = 0; j < 4; j++) {
                int sc = tx * 4 + j;
                float v = s[i][j];
                if (diag && sc > m) v = -INFINITY;
                sm->Ps[m][sc] = v;
            }
        }
        __syncthreads();

        {
            int m = tid >> 2, q4 = tid & 3;
            float pm = -INFINITY;
            int c0 = q4 * 16;
            #pragma unroll
            for (int c = 0; c < 16; c++) pm = fmaxf(pm, sm->Ps[m][c0 + c]);
            sm->red[m][q4] = pm;
        }
        __syncthreads();

        if (tid < 64) {
            int m = tid;
            float mnew = fmaxf(fmaxf(sm->red[m][0], sm->red[m][1]),
                               fmaxf(sm->red[m][2], sm->red[m][3]));
            mnew = fmaxf(mnew, sm->row_m[m]);
            sm->row_alpha[m] = __expf(sm->row_m[m] - mnew);
            sm->row_m[m] = mnew;
        }
        __syncthreads();

        {
            int m = tid >> 2, q4 = tid & 3;
            float mnew = sm->row_m[m];
            float ls = 0.0f;
            int c0 = q4 * 16;
            #pragma unroll
            for (int c = 0; c < 16; c++) {
                float p = __expf(sm->Ps[m][c0 + c] - mnew);
                sm->Ps[m][c0 + c] = p;
                ls += p;
            }
            sm->red[m][q4] = ls;
        }
        __syncthreads();

        if (tid < 64) {
            int m = tid;
            sm->row_l[m] = sm->row_l[m] * sm->row_alpha[m] +
                           (sm->red[m][0] + sm->red[m][1] + sm->red[m][2] + sm->red[m][3]);
        }

        #pragma unroll
        for (int i = 0; i < 4; i++) {
            float al = sm->row_alpha[ty * 4 + i];
            #pragma unroll
            for (int j = 0; j < 4; j++) acc[i][j] *= al;
        }

        #pragma unroll 8
        for (int kk = 0; kk < 64; kk++) {
            float a[4], bb[4];
            #pragma unroll
            for (int i = 0; i < 4; i++) a[i] = sm->Ps[ty * 4 + i][kk];
            #pragma unroll
            for (int j = 0; j < 4; j++) bb[j] = sm->Vs[kk][tx * 4 + j];
            #pragma unroll
            for (int i = 0; i < 4; i++)
                #pragma unroll
                for (int j = 0; j < 4; j++) acc[i][j] += a[i] * bb[j];
        }
    }
    __syncthreads();

    const int b = bh >> 4, h = bh & 15;
    #pragma unroll
    for (int i = 0; i < 4; i++) {
        int m = ty * 4 + i;
        float inv = 1.0f / sm->row_l[m];
        int tq = qb * 64 + m;
        float* dst = g_att + ((size_t)(b * T_ + tq)) * C_ + h * D_;
        #pragma unroll
        for (int j = 0; j < 4; j++) dst[tx * 4 + j] = acc[i][j] * inv;
    }
}

// ===========================================================================
extern "C" void kernel_launch(void* const* d_in, const int* in_sizes, int n_in,
                              void* d_out, int out_size)
{
    const float* x  = (const float*)d_in[0];
    const float* Wq = (const float*)d_in[1];
    const float* Wk = (const float*)d_in[2];
    const float* Wv = (const float*)d_in[3];
    const float* Wo = (const float*)d_in[4];
    const float* bo = (const float*)d_in[5];
    float* out = (float*)d_out;

    cudaFuncSetAttribute(attn_kernel, cudaFuncAttributeMaxDynamicSharedMemorySize,
                         (int)ATTN_SMEM_BYTES);
    cudaFuncSetAttribute(qkv_tc, cudaFuncAttributeMaxDynamicSharedMemorySize,
                         GEMM_SMEM_BYTES);
    cudaFuncSetAttribute(proj_tc, cudaFuncAttributeMaxDynamicSharedMemorySize,
                         GEMM_SMEM_BYTES);

    transpose_qkv_w<<<dim3(32, 2, 48), 256>>>(Wq, Wk, Wv);
    transpose_wo<<<dim3(32, 32), 256>>>(Wo);
    qkv_tc<<<dim3(64, 24), 256, GEMM_SMEM_BYTES>>>(x);
    attn_kernel<<<dim3(T_ / 64, B_ * H_), 256, ATTN_SMEM_BYTES>>>();
    proj_tc<<<dim3(64, 8), 256, GEMM_SMEM_BYTES>>>(out, bo);
}

// round 4
// speedup vs baseline: 5.9852x; 2.0978x over previous
#include <cuda_runtime.h>
#include <math.h>
#include <cstdint>

// Problem constants
#define B_ 4
#define T_ 2048
#define C_ 1024
#define H_ 16
#define D_ 64
#define BT_ (B_ * T_)           // 8192

// Scratch
__device__ float g_q[B_ * H_ * T_ * D_];    // [B,H,T,D]
__device__ float g_k[B_ * H_ * T_ * D_];
__device__ float g_v[B_ * H_ * T_ * D_];
__device__ float g_att[B_ * T_ * C_];       // [B,T,H*D]
__device__ float g_wt[3 * C_ * C_];         // K-major qkv weights [n=3072][k=1024]
__device__ float g_wot[C_ * C_];            // K-major Wo [n=1024][k=1024]

// ===========================================================================
// Helpers
// ===========================================================================
__device__ __forceinline__ float to_tf32(float x) {
    uint32_t r;
    asm("cvt.rna.tf32.f32 %0, %1;" : "=r"(r) : "f"(x));
    return __uint_as_float(r);
}

__device__ __forceinline__ void mma_tf32(float* c, const uint32_t* a, const uint32_t* b) {
    asm volatile(
        "mma.sync.aligned.m16n8k8.row.col.f32.tf32.tf32.f32 "
        "{%0,%1,%2,%3}, {%4,%5,%6,%7}, {%8,%9}, {%0,%1,%2,%3};\n"
        : "+f"(c[0]), "+f"(c[1]), "+f"(c[2]), "+f"(c[3])
        : "r"(a[0]), "r"(a[1]), "r"(a[2]), "r"(a[3]),
          "r"(b[0]), "r"(b[1]));
}

// ===========================================================================
// Dense GEMM machinery (unchanged from R3 — known good)
// ===========================================================================
#define TROW 36
#define TILE_F (128 * TROW)
#define BUF_F  (2 * TILE_F)
#define GEMM_SMEM_BYTES (2 * BUF_F * 4)

__device__ __forceinline__ void gemm_mainloop_mma(
    const float* __restrict__ A0, const float* __restrict__ B0,
    float* __restrict__ smf, float c[4][4][4])
{
    const int tid  = threadIdx.x;
    const int lane = tid & 31;
    const int wid  = tid >> 5;
    const int wm = (wid & 1) * 64;
    const int wn = (wid >> 1) * 32;
    const int qr = lane >> 2;
    const int qc = lane & 3;

    const int pc4 = tid & 7;
    const int pr  = tid >> 3;

    #pragma unroll
    for (int mf = 0; mf < 4; mf++)
        #pragma unroll
        for (int nf = 0; nf < 4; nf++)
            #pragma unroll
            for (int r = 0; r < 4; r++) c[mf][nf][r] = 0.0f;

    float4 pa[4], pb[4];

    #pragma unroll
    for (int l = 0; l < 4; l++) {
        pa[l] = *(const float4*)(A0 + (size_t)(pr + l * 32) * C_ + pc4 * 4);
        pb[l] = *(const float4*)(B0 + (size_t)(pr + l * 32) * C_ + pc4 * 4);
    }
    {
        float* sA = smf;
        float* sB = smf + TILE_F;
        #pragma unroll
        for (int l = 0; l < 4; l++) {
            float4 va = pa[l];
            va.x = to_tf32(va.x); va.y = to_tf32(va.y);
            va.z = to_tf32(va.z); va.w = to_tf32(va.w);
            *(float4*)(sA + (pr + l * 32) * TROW + pc4 * 4) = va;
            float4 vb = pb[l];
            vb.x = to_tf32(vb.x); vb.y = to_tf32(vb.y);
            vb.z = to_tf32(vb.z); vb.w = to_tf32(vb.w);
            *(float4*)(sB + (pr + l * 32) * TROW + pc4 * 4) = vb;
        }
    }
    __syncthreads();

    for (int kc = 0; kc < 32; kc++) {
        const int buf = kc & 1;
        float* sA = smf + buf * BUF_F;
        float* sB = sA + TILE_F;

        if (kc < 31) {
            const float* An = A0 + (kc + 1) * 32;
            const float* Bn = B0 + (kc + 1) * 32;
            #pragma unroll
            for (int l = 0; l < 4; l++) {
                pa[l] = *(const float4*)(An + (size_t)(pr + l * 32) * C_ + pc4 * 4);
                pb[l] = *(const float4*)(Bn + (size_t)(pr + l * 32) * C_ + pc4 * 4);
            }
        }

        #pragma unroll
        for (int ks = 0; ks < 4; ks++) {
            const int k0 = ks * 8;
            uint32_t a[4][4];
            #pragma unroll
            for (int mf = 0; mf < 4; mf++) {
                const float* ap = sA + (wm + mf * 16 + qr) * TROW + k0 + qc;
                a[mf][0] = __float_as_uint(ap[0]);
                a[mf][1] = __float_as_uint(ap[8 * TROW]);
                a[mf][2] = __float_as_uint(ap[4]);
                a[mf][3] = __float_as_uint(ap[8 * TROW + 4]);
            }
            uint32_t b[4][2];
            #pragma unroll
            for (int nf = 0; nf < 4; nf++) {
                const float* bp = sB + (wn + nf * 8 + qr) * TROW + k0 + qc;
                b[nf][0] = __float_as_uint(bp[0]);
                b[nf][1] = __float_as_uint(bp[4]);
            }
            #pragma unroll
            for (int mf = 0; mf < 4; mf++)
                #pragma unroll
                for (int nf = 0; nf < 4; nf++)
                    mma_tf32(c[mf][nf], a[mf], b[nf]);
        }

        if (kc < 31) {
            float* dA = smf + (buf ^ 1) * BUF_F;
            float* dB = dA + TILE_F;
            #pragma unroll
            for (int l = 0; l < 4; l++) {
                float4 va = pa[l];
                va.x = to_tf32(va.x); va.y = to_tf32(va.y);
                va.z = to_tf32(va.z); va.w = to_tf32(va.w);
                *(float4*)(dA + (pr + l * 32) * TROW + pc4 * 4) = va;
                float4 vb = pb[l];
                vb.x = to_tf32(vb.x); vb.y = to_tf32(vb.y);
                vb.z = to_tf32(vb.z); vb.w = to_tf32(vb.w);
                *(float4*)(dB + (pr + l * 32) * TROW + pc4 * 4) = vb;
            }
        }
        __syncthreads();
    }
}

// ===========================================================================
// Weight transposes
// ===========================================================================
__global__ __launch_bounds__(256) void transpose_qkv_w(
    const float* __restrict__ Wq, const float* __restrict__ Wk,
    const float* __restrict__ Wv)
{
    __shared__ float tile[32][33];
    const int z = blockIdx.z;
    const int which = z >> 4, h = z & 15;
    const float* W = (which == 0 ? Wq : (which == 1 ? Wk : Wv)) + (size_t)h * C_ * D_;
    const int c0 = blockIdx.x * 32;
    const int d0 = blockIdx.y * 32;
    const int tx = threadIdx.x & 31, ty = threadIdx.x >> 5;

    #pragma unroll
    for (int i = 0; i < 4; i++)
        tile[ty + i * 8][tx] = W[(size_t)(c0 + ty + i * 8) * D_ + d0 + tx];
    __syncthreads();
    const int nbase = which * 1024 + h * 64 + d0;
    #pragma unroll
    for (int i = 0; i < 4; i++)
        g_wt[(size_t)(nbase + ty + i * 8) * C_ + c0 + tx] = tile[tx][ty + i * 8];
}

__global__ __launch_bounds__(256) void transpose_wo(const float* __restrict__ Wo)
{
    __shared__ float tile[32][33];
    const int c0 = blockIdx.x * 32;
    const int n0 = blockIdx.y * 32;
    const int tx = threadIdx.x & 31, ty = threadIdx.x >> 5;
    #pragma unroll
    for (int i = 0; i < 4; i++)
        tile[ty + i * 8][tx] = Wo[(size_t)(c0 + ty + i * 8) * C_ + n0 + tx];
    __syncthreads();
    #pragma unroll
    for (int i = 0; i < 4; i++)
        g_wot[(size_t)(n0 + ty + i * 8) * C_ + c0 + tx] = tile[tx][ty + i * 8];
}

// ===========================================================================
// Kernel 1: QKV projection.  grid (64, 24), 256 threads.
// ===========================================================================
extern __shared__ __align__(16) float dyn_smf[];

__global__ __launch_bounds__(256) void qkv_tc(const float* __restrict__ x)
{
    const int mt = blockIdx.x, nt = blockIdx.y;
    const float* A0 = x + (size_t)mt * 128 * C_;
    const float* B0 = g_wt + (size_t)nt * 128 * C_;

    float c[4][4][4];
    gemm_mainloop_mma(A0, B0, dyn_smf, c);

    const int tid  = threadIdx.x;
    const int lane = tid & 31;
    const int wid  = tid >> 5;
    const int wm = (wid & 1) * 64;
    const int wn = (wid >> 1) * 32;
    const int qr = lane >> 2;
    const int qc = lane & 3;

    #pragma unroll
    for (int mf = 0; mf < 4; mf++) {
        #pragma unroll
        for (int half = 0; half < 2; half++) {
            const int m = mt * 128 + wm + mf * 16 + qr + half * 8;
            const int b = m >> 11, t = m & (T_ - 1);
            #pragma unroll
            for (int nf = 0; nf < 4; nf++) {
                const int n = nt * 128 + wn + nf * 8 + qc * 2;
                const int which = n >> 10;
                const int hh = (n >> 6) & 15;
                const int d = n & 63;
                float* op = (which == 0 ? g_q : (which == 1 ? g_k : g_v))
                            + ((size_t)(b * H_ + hh) * T_ + t) * D_ + d;
                float2 v = half == 0
                    ? make_float2(c[mf][nf][0], c[mf][nf][1])
                    : make_float2(c[mf][nf][2], c[mf][nf][3]);
                *(float2*)op = v;
            }
        }
    }
}

// ===========================================================================
// Kernel 3: output projection + bias.  grid (64, 8).
// ===========================================================================
__global__ __launch_bounds__(256) void proj_tc(float* __restrict__ out,
                                               const float* __restrict__ bo)
{
    const int mt = blockIdx.x, nt = blockIdx.y;
    const float* A0 = g_att + (size_t)mt * 128 * C_;
    const float* B0 = g_wot + (size_t)nt * 128 * C_;

    float c[4][4][4];
    gemm_mainloop_mma(A0, B0, dyn_smf, c);

    const int tid  = threadIdx.x;
    const int lane = tid & 31;
    const int wid  = tid >> 5;
    const int wm = (wid & 1) * 64;
    const int wn = (wid >> 1) * 32;
    const int qr = lane >> 2;
    const int qc = lane & 3;

    #pragma unroll
    for (int mf = 0; mf < 4; mf++) {
        #pragma unroll
        for (int half = 0; half < 2; half++) {
            const int m = mt * 128 + wm + mf * 16 + qr + half * 8;
            #pragma unroll
            for (int nf = 0; nf < 4; nf++) {
                const int n = nt * 128 + wn + nf * 8 + qc * 2;
                float2 bv = *(const float2*)(bo + n);
                float2 v = half == 0
                    ? make_float2(c[mf][nf][0] + bv.x, c[mf][nf][1] + bv.y)
                    : make_float2(c[mf][nf][2] + bv.x, c[mf][nf][3] + bv.y);
                *(float2*)(out + (size_t)m * C_ + n) = v;
            }
        }
    }
}

// ===========================================================================
// Kernel 2: tensor-core causal flash attention.
// BQ=128, BS=64, 256 threads (8 warps x 16 query rows).
// SMEM strides: Q/K/P = 68 (banks 4g+t, conflict-free), V = 72 (banks 8t+g).
// ===========================================================================
#define QSTR 68
#define KSTR 68
#define VSTR 72
#define PSTR 68
#define QS_OFF 0
#define KS_OFF (128 * QSTR)                 // 8704
#define VS_OFF (KS_OFF + 64 * KSTR)        // 13056
#define PS_OFF (VS_OFF + 64 * VSTR)        // 17664
#define ATTN_SMEM_F (PS_OFF + 128 * PSTR)  // 26368 floats
#define ATTN_SMEM_BYTES (ATTN_SMEM_F * 4)  // 105472 bytes

__global__ __launch_bounds__(256) void attn_mma_kernel()
{
    extern __shared__ __align__(16) float sf[];
    float* Qs = sf + QS_OFF;
    float* Ks = sf + KS_OFF;
    float* Vs = sf + VS_OFF;
    float* Ps = sf + PS_OFF;

    const int tid  = threadIdx.x;
    const int lane = tid & 31;
    const int w    = tid >> 5;          // warp 0..7
    const int g    = lane >> 2;         // 0..7
    const int t    = lane & 3;          // 0..3
    const int qb   = blockIdx.x;        // 0..15  (128 query rows each)
    const int bh   = blockIdx.y;        // 0..63

    const float* qp = g_q + (size_t)bh * T_ * D_;
    const float* kp = g_k + (size_t)bh * T_ * D_;
    const float* vp = g_v + (size_t)bh * T_ * D_;

    // load Q tile [128 x 64], scaled by 1/sqrt(D), tf32-rounded
    #pragma unroll
    for (int l = 0; l < 8; l++) {
        int idx = tid + l * 256;        // 0..2047 (float4 units)
        int r = idx >> 4, c4 = idx & 15;
        float4 v = *(const float4*)(qp + (size_t)(qb * 128 + r) * D_ + c4 * 4);
        v.x = to_tf32(v.x * 0.125f); v.y = to_tf32(v.y * 0.125f);
        v.z = to_tf32(v.z * 0.125f); v.w = to_tf32(v.w * 0.125f);
        *(float4*)(Qs + r * QSTR + c4 * 4) = v;
    }

    float o[8][4];
    #pragma unroll
    for (int nf = 0; nf < 8; nf++)
        #pragma unroll
        for (int r = 0; r < 4; r++) o[nf][r] = 0.0f;

    float mA = -1e30f, mB = -1e30f, lA = 0.0f, lB = 0.0f;
    const int rowA = qb * 128 + 16 * w + g;   // global query row (and rowA+8)

    const int sbmax = qb * 2 + 1;
    for (int sb = 0; sb <= sbmax; sb++) {
        __syncthreads();   // protect K/V from previous iteration's readers
        #pragma unroll
        for (int l = 0; l < 4; l++) {
            int idx = tid + l * 256;     // 0..1023 (float4 units)
            int r = idx >> 4, c4 = idx & 15;
            float4 kv = *(const float4*)(kp + (size_t)(sb * 64 + r) * D_ + c4 * 4);
            kv.x = to_tf32(kv.x); kv.y = to_tf32(kv.y);
            kv.z = to_tf32(kv.z); kv.w = to_tf32(kv.w);
            *(float4*)(Ks + r * KSTR + c4 * 4) = kv;
            float4 vv = *(const float4*)(vp + (size_t)(sb * 64 + r) * D_ + c4 * 4);
            vv.x = to_tf32(vv.x); vv.y = to_tf32(vv.y);
            vv.z = to_tf32(vv.z); vv.w = to_tf32(vv.w);
            *(float4*)(Vs + r * VSTR + c4 * 4) = vv;
        }
        __syncthreads();

        // ---- S = Q @ K^T  (warp rows [16w, 16w+16), all 64 cols) ----
        float s[8][4];
        #pragma unroll
        for (int nf = 0; nf < 8; nf++)
            #pragma unroll
            for (int r = 0; r < 4; r++) s[nf][r] = 0.0f;

        #pragma unroll
        for (int ks = 0; ks < 8; ks++) {
            const int k0 = ks * 8;
            uint32_t a[4];
            const float* ap = Qs + (16 * w + g) * QSTR + k0 + t;
            a[0] = __float_as_uint(ap[0]);
            a[1] = __float_as_uint(ap[8 * QSTR]);
            a[2] = __float_as_uint(ap[4]);
            a[3] = __float_as_uint(ap[8 * QSTR + 4]);
            #pragma unroll
            for (int nf = 0; nf < 8; nf++) {
                uint32_t b[2];
                const float* bp = Ks + (nf * 8 + g) * KSTR + k0 + t;
                b[0] = __float_as_uint(bp[0]);
                b[1] = __float_as_uint(bp[4]);
                mma_tf32(s[nf], a, b);
            }
        }

        // ---- causal mask (only when this warp's tile touches diagonal) ----
        if (sb * 64 + 63 > qb * 128 + 16 * w) {
            #pragma unroll
            for (int nf = 0; nf < 8; nf++) {
                const int c0 = sb * 64 + nf * 8 + 2 * t;
                if (c0 > rowA)     s[nf][0] = -1e30f;
                if (c0 + 1 > rowA) s[nf][1] = -1e30f;
                if (c0 > rowA + 8)     s[nf][2] = -1e30f;
                if (c0 + 1 > rowA + 8) s[nf][3] = -1e30f;
            }
        }

        // ---- online softmax (register-resident, 4-lane bfly per row) ----
        float mxA = -1e30f, mxB = -1e30f;
        #pragma unroll
        for (int nf = 0; nf < 8; nf++) {
            mxA = fmaxf(mxA, fmaxf(s[nf][0], s[nf][1]));
            mxB = fmaxf(mxB, fmaxf(s[nf][2], s[nf][3]));
        }
        mxA = fmaxf(mxA, __shfl_xor_sync(0xFFFFFFFF, mxA, 1));
        mxA = fmaxf(mxA, __shfl_xor_sync(0xFFFFFFFF, mxA, 2));
        mxB = fmaxf(mxB, __shfl_xor_sync(0xFFFFFFFF, mxB, 1));
        mxB = fmaxf(mxB, __shfl_xor_sync(0xFFFFFFFF, mxB, 2));

        const float mnA = fmaxf(mA, mxA);
        const float mnB = fmaxf(mB, mxB);
        const float aA = __expf(mA - mnA);
        const float aB = __expf(mB - mnB);
        mA = mnA; mB = mnB;

        float suA = 0.0f, suB = 0.0f;
        #pragma unroll
        for (int nf = 0; nf < 8; nf++) {
            float p0 = __expf(s[nf][0] - mnA);
            float p1 = __expf(s[nf][1] - mnA);
            float p2 = __expf(s[nf][2] - mnB);
            float p3 = __expf(s[nf][3] - mnB);
            suA += p0 + p1; suB += p2 + p3;
            s[nf][0] = to_tf32(p0); s[nf][1] = to_tf32(p1);
            s[nf][2] = to_tf32(p2); s[nf][3] = to_tf32(p3);
        }
        suA += __shfl_xor_sync(0xFFFFFFFF, suA, 1);
        suA += __shfl_xor_sync(0xFFFFFFFF, suA, 2);
        suB += __shfl_xor_sync(0xFFFFFFFF, suB, 1);
        suB += __shfl_xor_sync(0xFFFFFFFF, suB, 2);
        lA = lA * aA + suA;
        lB = lB * aB + suB;

        #pragma unroll
        for (int nf = 0; nf < 8; nf++) {
            o[nf][0] *= aA; o[nf][1] *= aA;
            o[nf][2] *= aB; o[nf][3] *= aB;
        }

        // ---- write P to warp-private SMEM rows (no block sync needed) ----
        #pragma unroll
        for (int nf = 0; nf < 8; nf++) {
            *(float2*)(Ps + (16 * w + g) * PSTR + nf * 8 + 2 * t) =
                make_float2(s[nf][0], s[nf][1]);
            *(float2*)(Ps + (16 * w + g + 8) * PSTR + nf * 8 + 2 * t) =
                make_float2(s[nf][2], s[nf][3]);
        }
        __syncwarp();

        // ---- O += P @ V ----
        #pragma unroll
        for (int ks = 0; ks < 8; ks++) {
            const int k0 = ks * 8;
            uint32_t a[4];
            const float* ap = Ps + (16 * w + g) * PSTR + k0 + t;
            a[0] = __float_as_uint(ap[0]);
            a[1] = __float_as_uint(ap[8 * PSTR]);
            a[2] = __float_as_uint(ap[4]);
            a[3] = __float_as_uint(ap[8 * PSTR + 4]);
            #pragma unroll
            for (int nf = 0; nf < 8; nf++) {
                uint32_t b[2];
                b[0] = __float_as_uint(Vs[(k0 + t) * VSTR + nf * 8 + g]);
                b[1] = __float_as_uint(Vs[(k0 + t + 4) * VSTR + nf * 8 + g]);
                mma_tf32(o[nf], a, b);
            }
        }
        __syncwarp();   // Ps reads done before next iteration's writes
    }

    // ---- epilogue: normalize and write to g_att [B,T,H*D] ----
    const int b = bh >> 4, h = bh & 15;
    const float invA = 1.0f / lA;
    const float invB = 1.0f / lB;
    const int rA = rowA, rB = rowA + 8;
    float* dstA = g_att + ((size_t)(b * T_ + rA)) * C_ + h * D_;
    float* dstB = g_att + ((size_t)(b * T_ + rB)) * C_ + h * D_;
    #pragma unroll
    for (int nf = 0; nf < 8; nf++) {
        const int cc = nf * 8 + 2 * t;
        *(float2*)(dstA + cc) = make_float2(o[nf][0] * invA, o[nf][1] * invA);
        *(float2*)(dstB + cc) = make_float2(o[nf][2] * invB, o[nf][3] * invB);
    }
}

// ===========================================================================
extern "C" void kernel_launch(void* const* d_in, const int* in_sizes, int n_in,
                              void* d_out, int out_size)
{
    const float* x  = (const float*)d_in[0];
    const float* Wq = (const float*)d_in[1];
    const float* Wk = (const float*)d_in[2];
    const float* Wv = (const float*)d_in[3];
    const float* Wo = (const float*)d_in[4];
    const float* bo = (const float*)d_in[5];
    float* out = (float*)d_out;

    cudaFuncSetAttribute(attn_mma_kernel, cudaFuncAttributeMaxDynamicSharedMemorySize,
                         ATTN_SMEM_BYTES);
    cudaFuncSetAttribute(qkv_tc, cudaFuncAttributeMaxDynamicSharedMemorySize,
                         GEMM_SMEM_BYTES);
    cudaFuncSetAttribute(proj_tc, cudaFuncAttributeMaxDynamicSharedMemorySize,
                         GEMM_SMEM_BYTES);

    transpose_qkv_w<<<dim3(32, 2, 48), 256>>>(Wq, Wk, Wv);
    transpose_wo<<<dim3(32, 32), 256>>>(Wo);
    qkv_tc<<<dim3(64, 24), 256, GEMM_SMEM_BYTES>>>(x);
    attn_mma_kernel<<<dim3(T_ / 128, B_ * H_), 256, ATTN_SMEM_BYTES>>>();
    proj_tc<<<dim3(64, 8), 256, GEMM_SMEM_BYTES>>>(out, bo);
}

// round 5
// speedup vs baseline: 6.1654x; 1.0301x over previous
#include <cuda_runtime.h>
#include <math.h>
#include <cstdint>

// Problem constants
#define B_ 4
#define T_ 2048
#define C_ 1024
#define H_ 16
#define D_ 64
#define BT_ (B_ * T_)           // 8192

// Scratch
__device__ float g_q[B_ * H_ * T_ * D_];    // [B,H,T,D]  (tf32-rounded)
__device__ float g_k[B_ * H_ * T_ * D_];
__device__ float g_v[B_ * H_ * T_ * D_];
__device__ float g_att[B_ * T_ * C_];       // [B,T,H*D]  (tf32-rounded)
__device__ float g_wt[3 * C_ * C_];         // K-major qkv weights (tf32-rounded)
__device__ float g_wot[C_ * C_];            // K-major Wo (tf32-rounded)
__device__ float g_xr[BT_ * C_];            // tf32-rounded x

// ===========================================================================
// Helpers
// ===========================================================================
__device__ __forceinline__ float to_tf32(float x) {
    uint32_t r;
    asm("cvt.rna.tf32.f32 %0, %1;" : "=r"(r) : "f"(x));
    return __uint_as_float(r);
}

__device__ __forceinline__ void mma_tf32(float* c, const uint32_t* a, const uint32_t* b) {
    asm volatile(
        "mma.sync.aligned.m16n8k8.row.col.f32.tf32.tf32.f32 "
        "{%0,%1,%2,%3}, {%4,%5,%6,%7}, {%8,%9}, {%0,%1,%2,%3};\n"
        : "+f"(c[0]), "+f"(c[1]), "+f"(c[2]), "+f"(c[3])
        : "r"(a[0]), "r"(a[1]), "r"(a[2]), "r"(a[3]),
          "r"(b[0]), "r"(b[1]));
}

__device__ __forceinline__ uint32_t smem_u32(const void* p) {
    return (uint32_t)__cvta_generic_to_shared(p);
}

#define CPA16(dst, src) \
    asm volatile("cp.async.ca.shared.global [%0], [%1], 16;" :: "r"(dst), "l"(src))
#define CP_COMMIT() asm volatile("cp.async.commit_group;" ::: "memory")
#define CP_WAIT0()  asm volatile("cp.async.wait_group 0;" ::: "memory")

// ===========================================================================
// Dense GEMM machinery: cp.async double-buffered, no cvts (inputs pre-rounded)
// ===========================================================================
#define TROW 36
#define TILE_F (128 * TROW)
#define BUF_F  (2 * TILE_F)
#define GEMM_SMEM_BYTES (2 * BUF_F * 4)

__device__ __forceinline__ void gemm_issue_chunk(
    const float* __restrict__ A0, const float* __restrict__ B0,
    uint32_t sb32, int kc, int buf, int pr, int pc4)
{
    const uint32_t abase = sb32 + (uint32_t)(buf * BUF_F) * 4;
    const uint32_t bbase = abase + (uint32_t)TILE_F * 4;
    #pragma unroll
    for (int l = 0; l < 4; l++) {
        const int r = pr + l * 32;
        const uint32_t so = (uint32_t)(r * TROW + pc4 * 4) * 4;
        CPA16(abase + so, A0 + (size_t)r * C_ + kc * 32 + pc4 * 4);
        CPA16(bbase + so, B0 + (size_t)r * C_ + kc * 32 + pc4 * 4);
    }
}

__device__ __forceinline__ void gemm_mainloop_mma(
    const float* __restrict__ A0, const float* __restrict__ B0,
    float* __restrict__ smf, float c[4][4][4])
{
    const int tid  = threadIdx.x;
    const int lane = tid & 31;
    const int wid  = tid >> 5;
    const int wm = (wid & 1) * 64;
    const int wn = (wid >> 1) * 32;
    const int qr = lane >> 2;
    const int qc = lane & 3;
    const int pc4 = tid & 7;
    const int pr  = tid >> 3;

    const uint32_t sb32 = smem_u32(smf);

    #pragma unroll
    for (int mf = 0; mf < 4; mf++)
        #pragma unroll
        for (int nf = 0; nf < 4; nf++)
            #pragma unroll
            for (int r = 0; r < 4; r++) c[mf][nf][r] = 0.0f;

    gemm_issue_chunk(A0, B0, sb32, 0, 0, pr, pc4);
    CP_COMMIT();

    for (int kc = 0; kc < 32; kc++) {
        const int buf = kc & 1;
        CP_WAIT0();
        __syncthreads();
        if (kc < 31) {
            gemm_issue_chunk(A0, B0, sb32, kc + 1, buf ^ 1, pr, pc4);
            CP_COMMIT();
        }

        float* sA = smf + buf * BUF_F;
        float* sB = sA + TILE_F;

        #pragma unroll
        for (int ks = 0; ks < 4; ks++) {
            const int k0 = ks * 8;
            uint32_t a[4][4];
            #pragma unroll
            for (int mf = 0; mf < 4; mf++) {
                const float* ap = sA + (wm + mf * 16 + qr) * TROW + k0 + qc;
                a[mf][0] = __float_as_uint(ap[0]);
                a[mf][1] = __float_as_uint(ap[8 * TROW]);
                a[mf][2] = __float_as_uint(ap[4]);
                a[mf][3] = __float_as_uint(ap[8 * TROW + 4]);
            }
            uint32_t b[4][2];
            #pragma unroll
            for (int nf = 0; nf < 4; nf++) {
                const float* bp = sB + (wn + nf * 8 + qr) * TROW + k0 + qc;
                b[nf][0] = __float_as_uint(bp[0]);
                b[nf][1] = __float_as_uint(bp[4]);
            }
            #pragma unroll
            for (int mf = 0; mf < 4; mf++)
                #pragma unroll
                for (int nf = 0; nf < 4; nf++)
                    mma_tf32(c[mf][nf], a[mf], b[nf]);
        }
    }
}

// ===========================================================================
// Producer-side rounding kernels
// ===========================================================================
__global__ __launch_bounds__(256) void round_x(const float* __restrict__ x)
{
    const int base = (blockIdx.x * 256 + threadIdx.x) * 4;
    #pragma unroll
    for (int l = 0; l < 1; l++) {
        float4 v = *(const float4*)(x + base);
        v.x = to_tf32(v.x); v.y = to_tf32(v.y);
        v.z = to_tf32(v.z); v.w = to_tf32(v.w);
        *(float4*)(g_xr + base) = v;
    }
}

__global__ __launch_bounds__(256) void transpose_qkv_w(
    const float* __restrict__ Wq, const float* __restrict__ Wk,
    const float* __restrict__ Wv)
{
    __shared__ float tile[32][33];
    const int z = blockIdx.z;
    const int which = z >> 4, h = z & 15;
    const float* W = (which == 0 ? Wq : (which == 1 ? Wk : Wv)) + (size_t)h * C_ * D_;
    const int c0 = blockIdx.x * 32;
    const int d0 = blockIdx.y * 32;
    const int tx = threadIdx.x & 31, ty = threadIdx.x >> 5;

    #pragma unroll
    for (int i = 0; i < 4; i++)
        tile[ty + i * 8][tx] = W[(size_t)(c0 + ty + i * 8) * D_ + d0 + tx];
    __syncthreads();
    const int nbase = which * 1024 + h * 64 + d0;
    #pragma unroll
    for (int i = 0; i < 4; i++)
        g_wt[(size_t)(nbase + ty + i * 8) * C_ + c0 + tx] = to_tf32(tile[tx][ty + i * 8]);
}

__global__ __launch_bounds__(256) void transpose_wo(const float* __restrict__ Wo)
{
    __shared__ float tile[32][33];
    const int c0 = blockIdx.x * 32;
    const int n0 = blockIdx.y * 32;
    const int tx = threadIdx.x & 31, ty = threadIdx.x >> 5;
    #pragma unroll
    for (int i = 0; i < 4; i++)
        tile[ty + i * 8][tx] = Wo[(size_t)(c0 + ty + i * 8) * C_ + n0 + tx];
    __syncthreads();
    #pragma unroll
    for (int i = 0; i < 4; i++)
        g_wot[(size_t)(n0 + ty + i * 8) * C_ + c0 + tx] = to_tf32(tile[tx][ty + i * 8]);
}

// ===========================================================================
// Kernel 1: QKV projection.  grid (64, 24), 256 threads.
// Epilogue writes tf32-rounded q/k/v (consumed as tf32 by attention).
// ===========================================================================
extern __shared__ __align__(16) float dyn_smf[];

__global__ __launch_bounds__(256, 2) void qkv_tc()
{
    const int mt = blockIdx.x, nt = blockIdx.y;
    const float* A0 = g_xr + (size_t)mt * 128 * C_;
    const float* B0 = g_wt + (size_t)nt * 128 * C_;

    float c[4][4][4];
    gemm_mainloop_mma(A0, B0, dyn_smf, c);

    const int tid  = threadIdx.x;
    const int lane = tid & 31;
    const int wid  = tid >> 5;
    const int wm = (wid & 1) * 64;
    const int wn = (wid >> 1) * 32;
    const int qr = lane >> 2;
    const int qc = lane & 3;

    #pragma unroll
    for (int mf = 0; mf < 4; mf++) {
        #pragma unroll
        for (int half = 0; half < 2; half++) {
            const int m = mt * 128 + wm + mf * 16 + qr + half * 8;
            const int b = m >> 11, t = m & (T_ - 1);
            #pragma unroll
            for (int nf = 0; nf < 4; nf++) {
                const int n = nt * 128 + wn + nf * 8 + qc * 2;
                const int which = n >> 10;
                const int hh = (n >> 6) & 15;
                const int d = n & 63;
                float* op = (which == 0 ? g_q : (which == 1 ? g_k : g_v))
                            + ((size_t)(b * H_ + hh) * T_ + t) * D_ + d;
                float2 v = half == 0
                    ? make_float2(to_tf32(c[mf][nf][0]), to_tf32(c[mf][nf][1]))
                    : make_float2(to_tf32(c[mf][nf][2]), to_tf32(c[mf][nf][3]));
                *(float2*)op = v;
            }
        }
    }
}

// ===========================================================================
// Kernel 3: output projection + bias.  grid (64, 8).
// ===========================================================================
__global__ __launch_bounds__(256, 2) void proj_tc(float* __restrict__ out,
                                                  const float* __restrict__ bo)
{
    const int mt = blockIdx.x, nt = blockIdx.y;
    const float* A0 = g_att + (size_t)mt * 128 * C_;
    const float* B0 = g_wot + (size_t)nt * 128 * C_;

    float c[4][4][4];
    gemm_mainloop_mma(A0, B0, dyn_smf, c);

    const int tid  = threadIdx.x;
    const int lane = tid & 31;
    const int wid  = tid >> 5;
    const int wm = (wid & 1) * 64;
    const int wn = (wid >> 1) * 32;
    const int qr = lane >> 2;
    const int qc = lane & 3;

    #pragma unroll
    for (int mf = 0; mf < 4; mf++) {
        #pragma unroll
        for (int half = 0; half < 2; half++) {
            const int m = mt * 128 + wm + mf * 16 + qr + half * 8;
            #pragma unroll
            for (int nf = 0; nf < 4; nf++) {
                const int n = nt * 128 + wn + nf * 8 + qc * 2;
                float2 bv = *(const float2*)(bo + n);
                float2 v = half == 0
                    ? make_float2(c[mf][nf][0] + bv.x, c[mf][nf][1] + bv.y)
                    : make_float2(c[mf][nf][2] + bv.x, c[mf][nf][3] + bv.y);
                *(float2*)(out + (size_t)m * C_ + n) = v;
            }
        }
    }
}

// ===========================================================================
// Kernel 2: tensor-core causal flash attention.
// BQ=128, BS=64, 256 threads.  Q fragments register-resident; K/V double-
// buffered via cp.async with ONE __syncthreads per s-block.
// SMEM (floats): Ps[128*68] | Ks[2][64*68] | Vs[2][64*72]
// ===========================================================================
#define PSTR 68
#define KSTR 68
#define VSTR 72
#define PS_OFF 0
#define KS_OFF (128 * PSTR)              // 8704
#define KBUF   (64 * KSTR)               // 4352
#define VS_OFF (KS_OFF + 2 * KBUF)       // 17408
#define VBUF   (64 * VSTR)               // 4608
#define ATTN_SMEM_F (VS_OFF + 2 * VBUF)  // 26624 floats
#define ATTN_SMEM_BYTES (ATTN_SMEM_F * 4)  // 106496 bytes

__device__ __forceinline__ void attn_issue_kv(
    const float* __restrict__ kp, const float* __restrict__ vp,
    uint32_t sb32, int sb, int buf, int tid)
{
    const float* ksrc = kp + (size_t)(sb * 64) * D_;
    const float* vsrc = vp + (size_t)(sb * 64) * D_;
    const uint32_t kdst = sb32 + (uint32_t)(KS_OFF + buf * KBUF) * 4;
    const uint32_t vdst = sb32 + (uint32_t)(VS_OFF + buf * VBUF) * 4;
    #pragma unroll
    for (int l = 0; l < 4; l++) {
        const int idx = tid + l * 256;
        const int r = idx >> 4, c4 = idx & 15;
        CPA16(kdst + (uint32_t)(r * KSTR + c4 * 4) * 4, ksrc + r * D_ + c4 * 4);
        CPA16(vdst + (uint32_t)(r * VSTR + c4 * 4) * 4, vsrc + r * D_ + c4 * 4);
    }
}

__global__ __launch_bounds__(256, 2) void attn_mma_kernel()
{
    extern __shared__ __align__(16) float sf[];
    float* Ps = sf + PS_OFF;

    const int tid  = threadIdx.x;
    const int lane = tid & 31;
    const int w    = tid >> 5;
    const int g    = lane >> 2;
    const int t    = lane & 3;
    const int qb   = blockIdx.x;        // 0..15
    const int bh   = blockIdx.y;        // 0..63

    const float* qp = g_q + (size_t)bh * T_ * D_;
    const float* kp = g_k + (size_t)bh * T_ * D_;
    const float* vp = g_v + (size_t)bh * T_ * D_;
    const uint32_t sb32 = smem_u32(sf);

    // kick off K/V for sb=0 immediately
    attn_issue_kv(kp, vp, sb32, 0, 0, tid);
    CP_COMMIT();

    // stage Q (scaled by exact 0.125 — preserves tf32 rounding) into Ps
    #pragma unroll
    for (int l = 0; l < 8; l++) {
        const int idx = tid + l * 256;
        const int r = idx >> 4, c4 = idx & 15;
        float4 v = *(const float4*)(qp + (size_t)(qb * 128 + r) * D_ + c4 * 4);
        v.x *= 0.125f; v.y *= 0.125f; v.z *= 0.125f; v.w *= 0.125f;
        *(float4*)(Ps + r * PSTR + c4 * 4) = v;
    }
    __syncthreads();

    // extract Q fragments to registers (own warp band only)
    uint32_t qf[8][4];
    #pragma unroll
    for (int ks = 0; ks < 8; ks++) {
        const float* ap = Ps + (16 * w + g) * PSTR + ks * 8 + t;
        qf[ks][0] = __float_as_uint(ap[0]);
        qf[ks][1] = __float_as_uint(ap[8 * PSTR]);
        qf[ks][2] = __float_as_uint(ap[4]);
        qf[ks][3] = __float_as_uint(ap[8 * PSTR + 4]);
    }

    float o[8][4];
    #pragma unroll
    for (int nf = 0; nf < 8; nf++)
        #pragma unroll
        for (int r = 0; r < 4; r++) o[nf][r] = 0.0f;

    float mA = -1e30f, mB = -1e30f, lA = 0.0f, lB = 0.0f;
    const int rowA = qb * 128 + 16 * w + g;

    const int sbmax = qb * 2 + 1;
    for (int sb = 0; sb <= sbmax; sb++) {
        const int buf = sb & 1;
        CP_WAIT0();
        __syncthreads();   // sb data visible to all; prev readers done
        if (sb < sbmax) {
            attn_issue_kv(kp, vp, sb32, sb + 1, buf ^ 1, tid);
            CP_COMMIT();
        }
        float* Ks = sf + KS_OFF + buf * KBUF;
        float* Vs = sf + VS_OFF + buf * VBUF;

        // ---- S = Q @ K^T ----
        float s[8][4];
        #pragma unroll
        for (int nf = 0; nf < 8; nf++)
            #pragma unroll
            for (int r = 0; r < 4; r++) s[nf][r] = 0.0f;

        #pragma unroll
        for (int ks = 0; ks < 8; ks++) {
            const int k0 = ks * 8;
            #pragma unroll
            for (int nf = 0; nf < 8; nf++) {
                uint32_t b[2];
                const float* bp = Ks + (nf * 8 + g) * KSTR + k0 + t;
                b[0] = __float_as_uint(bp[0]);
                b[1] = __float_as_uint(bp[4]);
                mma_tf32(s[nf], qf[ks], b);
            }
        }

        // ---- causal mask ----
        if (sb * 64 + 63 > qb * 128 + 16 * w) {
            #pragma unroll
            for (int nf = 0; nf < 8; nf++) {
                const int c0 = sb * 64 + nf * 8 + 2 * t;
                if (c0 > rowA)     s[nf][0] = -1e30f;
                if (c0 + 1 > rowA) s[nf][1] = -1e30f;
                if (c0 > rowA + 8)     s[nf][2] = -1e30f;
                if (c0 + 1 > rowA + 8) s[nf][3] = -1e30f;
            }
        }

        // ---- online softmax ----
        float mxA = -1e30f, mxB = -1e30f;
        #pragma unroll
        for (int nf = 0; nf < 8; nf++) {
            mxA = fmaxf(mxA, fmaxf(s[nf][0], s[nf][1]));
            mxB = fmaxf(mxB, fmaxf(s[nf][2], s[nf][3]));
        }
        mxA = fmaxf(mxA, __shfl_xor_sync(0xFFFFFFFF, mxA, 1));
        mxA = fmaxf(mxA, __shfl_xor_sync(0xFFFFFFFF, mxA, 2));
        mxB = fmaxf(mxB, __shfl_xor_sync(0xFFFFFFFF, mxB, 1));
        mxB = fmaxf(mxB, __shfl_xor_sync(0xFFFFFFFF, mxB, 2));

        const float mnA = fmaxf(mA, mxA);
        const float mnB = fmaxf(mB, mxB);
        const float aA = __expf(mA - mnA);
        const float aB = __expf(mB - mnB);
        mA = mnA; mB = mnB;

        float suA = 0.0f, suB = 0.0f;
        #pragma unroll
        for (int nf = 0; nf < 8; nf++) {
            float p0 = __expf(s[nf][0] - mnA);
            float p1 = __expf(s[nf][1] - mnA);
            float p2 = __expf(s[nf][2] - mnB);
            float p3 = __expf(s[nf][3] - mnB);
            suA += p0 + p1; suB += p2 + p3;
            s[nf][0] = to_tf32(p0); s[nf][1] = to_tf32(p1);
            s[nf][2] = to_tf32(p2); s[nf][3] = to_tf32(p3);
        }
        suA += __shfl_xor_sync(0xFFFFFFFF, suA, 1);
        suA += __shfl_xor_sync(0xFFFFFFFF, suA, 2);
        suB += __shfl_xor_sync(0xFFFFFFFF, suB, 1);
        suB += __shfl_xor_sync(0xFFFFFFFF, suB, 2);
        lA = lA * aA + suA;
        lB = lB * aB + suB;

        #pragma unroll
        for (int nf = 0; nf < 8; nf++) {
            o[nf][0] *= aA; o[nf][1] *= aA;
            o[nf][2] *= aB; o[nf][3] *= aB;
        }

        // ---- P to warp-private SMEM rows ----
        #pragma unroll
        for (int nf = 0; nf < 8; nf++) {
            *(float2*)(Ps + (16 * w + g) * PSTR + nf * 8 + 2 * t) =
                make_float2(s[nf][0], s[nf][1]);
            *(float2*)(Ps + (16 * w + g + 8) * PSTR + nf * 8 + 2 * t) =
                make_float2(s[nf][2], s[nf][3]);
        }
        __syncwarp();

        // ---- O += P @ V ----
        #pragma unroll
        for (int ks = 0; ks < 8; ks++) {
            const int k0 = ks * 8;
            uint32_t a[4];
            const float* ap = Ps + (16 * w + g) * PSTR + k0 + t;
            a[0] = __float_as_uint(ap[0]);
            a[1] = __float_as_uint(ap[8 * PSTR]);
            a[2] = __float_as_uint(ap[4]);
            a[3] = __float_as_uint(ap[8 * PSTR + 4]);
            #pragma unroll
            for (int nf = 0; nf < 8; nf++) {
                uint32_t b[2];
                b[0] = __float_as_uint(Vs[(k0 + t) * VSTR + nf * 8 + g]);
                b[1] = __float_as_uint(Vs[(k0 + t + 4) * VSTR + nf * 8 + g]);
                mma_tf32(o[nf], a, b);
            }
        }
        // next iteration's __syncthreads orders Ps reads before rewrites
    }

    // ---- epilogue: normalize, tf32-round (proj consumes as tf32) ----
    const int b = bh >> 4, h = bh & 15;
    const float invA = 1.0f / lA;
    const float invB = 1.0f / lB;
    float* dstA = g_att + ((size_t)(b * T_ + rowA)) * C_ + h * D_;
    float* dstB = g_att + ((size_t)(b * T_ + rowA + 8)) * C_ + h * D_;
    #pragma unroll
    for (int nf = 0; nf < 8; nf++) {
        const int cc = nf * 8 + 2 * t;
        *(float2*)(dstA + cc) =
            make_float2(to_tf32(o[nf][0] * invA), to_tf32(o[nf][1] * invA));
        *(float2*)(dstB + cc) =
            make_float2(to_tf32(o[nf][2] * invB), to_tf32(o[nf][3] * invB));
    }
}

// ===========================================================================
extern "C" void kernel_launch(void* const* d_in, const int* in_sizes, int n_in,
                              void* d_out, int out_size)
{
    const float* x  = (const float*)d_in[0];
    const float* Wq = (const float*)d_in[1];
    const float* Wk = (const float*)d_in[2];
    const float* Wv = (const float*)d_in[3];
    const float* Wo = (const float*)d_in[4];
    const float* bo = (const float*)d_in[5];
    float* out = (float*)d_out;

    cudaFuncSetAttribute(attn_mma_kernel, cudaFuncAttributeMaxDynamicSharedMemorySize,
                         ATTN_SMEM_BYTES);
    cudaFuncSetAttribute(qkv_tc, cudaFuncAttributeMaxDynamicSharedMemorySize,
                         GEMM_SMEM_BYTES);
    cudaFuncSetAttribute(proj_tc, cudaFuncAttributeMaxDynamicSharedMemorySize,
                         GEMM_SMEM_BYTES);

    round_x<<<BT_ * C_ / (256 * 4), 256>>>(x);
    transpose_qkv_w<<<dim3(32, 2, 48), 256>>>(Wq, Wk, Wv);
    transpose_wo<<<dim3(32, 32), 256>>>(Wo);
    qkv_tc<<<dim3(64, 24), 256, GEMM_SMEM_BYTES>>>();
    attn_mma_kernel<<<dim3(T_ / 128, B_ * H_), 256, ATTN_SMEM_BYTES>>>();
    proj_tc<<<dim3(64, 8), 256, GEMM_SMEM_BYTES>>>(out, bo);
}

// round 6
// speedup vs baseline: 6.5211x; 1.0577x over previous
#include <cuda_runtime.h>
#include <math.h>
#include <cstdint>

// Problem constants
#define B_ 4
#define T_ 2048
#define C_ 1024
#define H_ 16
#define D_ 64
#define BT_ (B_ * T_)           // 8192

// Scratch
__device__ float g_q[B_ * H_ * T_ * D_];    // [B,H,T,D]  (tf32-rounded)
__device__ float g_k[B_ * H_ * T_ * D_];
__device__ float g_v[B_ * H_ * T_ * D_];
__device__ float g_att[B_ * T_ * C_];       // [B,T,H*D]  (tf32-rounded)
__device__ float g_wt[3 * C_ * C_];         // K-major qkv weights (tf32-rounded)
__device__ float g_wot[C_ * C_];            // K-major Wo (tf32-rounded)
__device__ float g_xr[BT_ * C_];            // tf32-rounded x

// ===========================================================================
// Helpers
// ===========================================================================
__device__ __forceinline__ float to_tf32(float x) {
    uint32_t r;
    asm("cvt.rna.tf32.f32 %0, %1;" : "=r"(r) : "f"(x));
    return __uint_as_float(r);
}

__device__ __forceinline__ void mma_tf32(float* c, const uint32_t* a, const uint32_t* b) {
    asm volatile(
        "mma.sync.aligned.m16n8k8.row.col.f32.tf32.tf32.f32 "
        "{%0,%1,%2,%3}, {%4,%5,%6,%7}, {%8,%9}, {%0,%1,%2,%3};\n"
        : "+f"(c[0]), "+f"(c[1]), "+f"(c[2]), "+f"(c[3])
        : "r"(a[0]), "r"(a[1]), "r"(a[2]), "r"(a[3]),
          "r"(b[0]), "r"(b[1]));
}

__device__ __forceinline__ uint32_t smem_u32(const void* p) {
    return (uint32_t)__cvta_generic_to_shared(p);
}

#define CPA16(dst, src) \
    asm volatile("cp.async.ca.shared.global [%0], [%1], 16;" :: "r"(dst), "l"(src))
#define CP_COMMIT() asm volatile("cp.async.commit_group;" ::: "memory")
#define CP_WAIT0()  asm volatile("cp.async.wait_group 0;" ::: "memory")

// ===========================================================================
// Dense GEMM: 128 threads / 4 warps, warp tile 64x64, block 128x128x32.
// cp.async double-buffered.  Tensor-bound by design (1.0 LDS-word per MMA).
// ===========================================================================
#define TROW 36
#define TILE_F (128 * TROW)
#define BUF_F  (2 * TILE_F)
#define GEMM_SMEM_BYTES (2 * BUF_F * 4)

__device__ __forceinline__ void gemm_issue_chunk(
    const float* __restrict__ A0, const float* __restrict__ B0,
    uint32_t sb32, int kc, int buf, int pr, int pc4)
{
    const uint32_t abase = sb32 + (uint32_t)(buf * BUF_F) * 4;
    const uint32_t bbase = abase + (uint32_t)TILE_F * 4;
    #pragma unroll
    for (int l = 0; l < 8; l++) {
        const int r = pr + l * 16;
        const uint32_t so = (uint32_t)(r * TROW + pc4 * 4) * 4;
        CPA16(abase + so, A0 + (size_t)r * C_ + kc * 32 + pc4 * 4);
        CPA16(bbase + so, B0 + (size_t)r * C_ + kc * 32 + pc4 * 4);
    }
}

__device__ __forceinline__ void gemm_mainloop_mma(
    const float* __restrict__ A0, const float* __restrict__ B0,
    float* __restrict__ smf, float c[4][8][4])
{
    const int tid  = threadIdx.x;
    const int lane = tid & 31;
    const int wid  = tid >> 5;           // 0..3
    const int wm = (wid & 1) * 64;
    const int wn = (wid >> 1) * 64;
    const int qr = lane >> 2;
    const int qc = lane & 3;
    const int pc4 = tid & 7;
    const int pr  = tid >> 3;            // 0..15

    const uint32_t sb32 = smem_u32(smf);

    #pragma unroll
    for (int mf = 0; mf < 4; mf++)
        #pragma unroll
        for (int nf = 0; nf < 8; nf++)
            #pragma unroll
            for (int r = 0; r < 4; r++) c[mf][nf][r] = 0.0f;

    gemm_issue_chunk(A0, B0, sb32, 0, 0, pr, pc4);
    CP_COMMIT();

    for (int kc = 0; kc < 32; kc++) {
        const int buf = kc & 1;
        CP_WAIT0();
        __syncthreads();
        if (kc < 31) {
            gemm_issue_chunk(A0, B0, sb32, kc + 1, buf ^ 1, pr, pc4);
            CP_COMMIT();
        }

        float* sA = smf + buf * BUF_F;
        float* sB = sA + TILE_F;

        #pragma unroll
        for (int ks = 0; ks < 4; ks++) {
            const int k0 = ks * 8;
            uint32_t a[4][4];
            #pragma unroll
            for (int mf = 0; mf < 4; mf++) {
                const float* ap = sA + (wm + mf * 16 + qr) * TROW + k0 + qc;
                a[mf][0] = __float_as_uint(ap[0]);
                a[mf][1] = __float_as_uint(ap[8 * TROW]);
                a[mf][2] = __float_as_uint(ap[4]);
                a[mf][3] = __float_as_uint(ap[8 * TROW + 4]);
            }
            uint32_t b[8][2];
            #pragma unroll
            for (int nf = 0; nf < 8; nf++) {
                const float* bp = sB + (wn + nf * 8 + qr) * TROW + k0 + qc;
                b[nf][0] = __float_as_uint(bp[0]);
                b[nf][1] = __float_as_uint(bp[4]);
            }
            #pragma unroll
            for (int mf = 0; mf < 4; mf++)
                #pragma unroll
                for (int nf = 0; nf < 8; nf++)
                    mma_tf32(c[mf][nf], a[mf], b[nf]);
        }
    }
}

// ===========================================================================
// Producer-side rounding kernels
// ===========================================================================
__global__ __launch_bounds__(256) void round_x(const float* __restrict__ x)
{
    const int base = (blockIdx.x * 256 + threadIdx.x) * 4;
    float4 v = *(const float4*)(x + base);
    v.x = to_tf32(v.x); v.y = to_tf32(v.y);
    v.z = to_tf32(v.z); v.w = to_tf32(v.w);
    *(float4*)(g_xr + base) = v;
}

__global__ __launch_bounds__(256) void transpose_qkv_w(
    const float* __restrict__ Wq, const float* __restrict__ Wk,
    const float* __restrict__ Wv)
{
    __shared__ float tile[32][33];
    const int z = blockIdx.z;
    const int which = z >> 4, h = z & 15;
    const float* W = (which == 0 ? Wq : (which == 1 ? Wk : Wv)) + (size_t)h * C_ * D_;
    const int c0 = blockIdx.x * 32;
    const int d0 = blockIdx.y * 32;
    const int tx = threadIdx.x & 31, ty = threadIdx.x >> 5;

    #pragma unroll
    for (int i = 0; i < 4; i++)
        tile[ty + i * 8][tx] = W[(size_t)(c0 + ty + i * 8) * D_ + d0 + tx];
    __syncthreads();
    const int nbase = which * 1024 + h * 64 + d0;
    #pragma unroll
    for (int i = 0; i < 4; i++)
        g_wt[(size_t)(nbase + ty + i * 8) * C_ + c0 + tx] = to_tf32(tile[tx][ty + i * 8]);
}

__global__ __launch_bounds__(256) void transpose_wo(const float* __restrict__ Wo)
{
    __shared__ float tile[32][33];
    const int c0 = blockIdx.x * 32;
    const int n0 = blockIdx.y * 32;
    const int tx = threadIdx.x & 31, ty = threadIdx.x >> 5;
    #pragma unroll
    for (int i = 0; i < 4; i++)
        tile[ty + i * 8][tx] = Wo[(size_t)(c0 + ty + i * 8) * C_ + n0 + tx];
    __syncthreads();
    #pragma unroll
    for (int i = 0; i < 4; i++)
        g_wot[(size_t)(n0 + ty + i * 8) * C_ + c0 + tx] = to_tf32(tile[tx][ty + i * 8]);
}

// ===========================================================================
// Kernel 1: QKV projection.  grid (64, 24), 128 threads.
// ===========================================================================
extern __shared__ __align__(16) float dyn_smf[];

__global__ __launch_bounds__(128, 2) void qkv_tc()
{
    const int mt = blockIdx.x, nt = blockIdx.y;
    const float* A0 = g_xr + (size_t)mt * 128 * C_;
    const float* B0 = g_wt + (size_t)nt * 128 * C_;

    float c[4][8][4];
    gemm_mainloop_mma(A0, B0, dyn_smf, c);

    const int tid  = threadIdx.x;
    const int lane = tid & 31;
    const int wid  = tid >> 5;
    const int wm = (wid & 1) * 64;
    const int wn = (wid >> 1) * 64;
    const int qr = lane >> 2;
    const int qc = lane & 3;

    // each warp's 64 n-cols live in exactly one head block (base mult of 64)
    const int nb0 = nt * 128 + wn;
    const int which = nb0 >> 10;
    const int hh = (nb0 >> 6) & 15;
    float* outb = (which == 0 ? g_q : (which == 1 ? g_k : g_v));

    #pragma unroll
    for (int mf = 0; mf < 4; mf++) {
        #pragma unroll
        for (int half = 0; half < 2; half++) {
            const int m = mt * 128 + wm + mf * 16 + qr + half * 8;
            const int b = m >> 11, t = m & (T_ - 1);
            float* op = outb + ((size_t)(b * H_ + hh) * T_ + t) * D_;
            #pragma unroll
            for (int nf = 0; nf < 8; nf++) {
                const int d = nf * 8 + qc * 2;
                float2 v = half == 0
                    ? make_float2(to_tf32(c[mf][nf][0]), to_tf32(c[mf][nf][1]))
                    : make_float2(to_tf32(c[mf][nf][2]), to_tf32(c[mf][nf][3]));
                *(float2*)(op + d) = v;
            }
        }
    }
}

// ===========================================================================
// Kernel 3: output projection + bias.  grid (64, 8), 128 threads.
// ===========================================================================
__global__ __launch_bounds__(128, 2) void proj_tc(float* __restrict__ out,
                                                  const float* __restrict__ bo)
{
    const int mt = blockIdx.x, nt = blockIdx.y;
    const float* A0 = g_att + (size_t)mt * 128 * C_;
    const float* B0 = g_wot + (size_t)nt * 128 * C_;

    float c[4][8][4];
    gemm_mainloop_mma(A0, B0, dyn_smf, c);

    const int tid  = threadIdx.x;
    const int lane = tid & 31;
    const int wid  = tid >> 5;
    const int wm = (wid & 1) * 64;
    const int wn = (wid >> 1) * 64;
    const int qr = lane >> 2;
    const int qc = lane & 3;

    #pragma unroll
    for (int mf = 0; mf < 4; mf++) {
        #pragma unroll
        for (int half = 0; half < 2; half++) {
            const int m = mt * 128 + wm + mf * 16 + qr + half * 8;
            #pragma unroll
            for (int nf = 0; nf < 8; nf++) {
                const int n = nt * 128 + wn + nf * 8 + qc * 2;
                float2 bv = *(const float2*)(bo + n);
                float2 v = half == 0
                    ? make_float2(c[mf][nf][0] + bv.x, c[mf][nf][1] + bv.y)
                    : make_float2(c[mf][nf][2] + bv.x, c[mf][nf][3] + bv.y);
                *(float2*)(out + (size_t)m * C_ + n) = v;
            }
        }
    }
}

// ===========================================================================
// Kernel 2: tensor-core causal flash attention (unchanged from R5).
// BQ=128, BS=64, 256 threads.  Q fragments register-resident; K/V double-
// buffered via cp.async with ONE __syncthreads per s-block.
// ===========================================================================
#define PSTR 68
#define KSTR 68
#define VSTR 72
#define PS_OFF 0
#define KS_OFF (128 * PSTR)              // 8704
#define KBUF   (64 * KSTR)               // 4352
#define VS_OFF (KS_OFF + 2 * KBUF)       // 17408
#define VBUF   (64 * VSTR)               // 4608
#define ATTN_SMEM_F (VS_OFF + 2 * VBUF)  // 26624 floats
#define ATTN_SMEM_BYTES (ATTN_SMEM_F * 4)  // 106496 bytes

__device__ __forceinline__ void attn_issue_kv(
    const float* __restrict__ kp, const float* __restrict__ vp,
    uint32_t sb32, int sb, int buf, int tid)
{
    const float* ksrc = kp + (size_t)(sb * 64) * D_;
    const float* vsrc = vp + (size_t)(sb * 64) * D_;
    const uint32_t kdst = sb32 + (uint32_t)(KS_OFF + buf * KBUF) * 4;
    const uint32_t vdst = sb32 + (uint32_t)(VS_OFF + buf * VBUF) * 4;
    #pragma unroll
    for (int l = 0; l < 4; l++) {
        const int idx = tid + l * 256;
        const int r = idx >> 4, c4 = idx & 15;
        CPA16(kdst + (uint32_t)(r * KSTR + c4 * 4) * 4, ksrc + r * D_ + c4 * 4);
        CPA16(vdst + (uint32_t)(r * VSTR + c4 * 4) * 4, vsrc + r * D_ + c4 * 4);
    }
}

__global__ __launch_bounds__(256, 2) void attn_mma_kernel()
{
    extern __shared__ __align__(16) float sf[];
    float* Ps = sf + PS_OFF;

    const int tid  = threadIdx.x;
    const int lane = tid & 31;
    const int w    = tid >> 5;
    const int g    = lane >> 2;
    const int t    = lane & 3;
    const int qb   = blockIdx.x;        // 0..15
    const int bh   = blockIdx.y;        // 0..63

    const float* qp = g_q + (size_t)bh * T_ * D_;
    const float* kp = g_k + (size_t)bh * T_ * D_;
    const float* vp = g_v + (size_t)bh * T_ * D_;
    const uint32_t sb32 = smem_u32(sf);

    attn_issue_kv(kp, vp, sb32, 0, 0, tid);
    CP_COMMIT();

    #pragma unroll
    for (int l = 0; l < 8; l++) {
        const int idx = tid + l * 256;
        const int r = idx >> 4, c4 = idx & 15;
        float4 v = *(const float4*)(qp + (size_t)(qb * 128 + r) * D_ + c4 * 4);
        v.x *= 0.125f; v.y *= 0.125f; v.z *= 0.125f; v.w *= 0.125f;
        *(float4*)(Ps + r * PSTR + c4 * 4) = v;
    }
    __syncthreads();

    uint32_t qf[8][4];
    #pragma unroll
    for (int ks = 0; ks < 8; ks++) {
        const float* ap = Ps + (16 * w + g) * PSTR + ks * 8 + t;
        qf[ks][0] = __float_as_uint(ap[0]);
        qf[ks][1] = __float_as_uint(ap[8 * PSTR]);
        qf[ks][2] = __float_as_uint(ap[4]);
        qf[ks][3] = __float_as_uint(ap[8 * PSTR + 4]);
    }

    float o[8][4];
    #pragma unroll
    for (int nf = 0; nf < 8; nf++)
        #pragma unroll
        for (int r = 0; r < 4; r++) o[nf][r] = 0.0f;

    float mA = -1e30f, mB = -1e30f, lA = 0.0f, lB = 0.0f;
    const int rowA = qb * 128 + 16 * w + g;

    const int sbmax = qb * 2 + 1;
    for (int sb = 0; sb <= sbmax; sb++) {
        const int buf = sb & 1;
        CP_WAIT0();
        __syncthreads();
        if (sb < sbmax) {
            attn_issue_kv(kp, vp, sb32, sb + 1, buf ^ 1, tid);
            CP_COMMIT();
        }
        float* Ks = sf + KS_OFF + buf * KBUF;
        float* Vs = sf + VS_OFF + buf * VBUF;

        float s[8][4];
        #pragma unroll
        for (int nf = 0; nf < 8; nf++)
            #pragma unroll
            for (int r = 0; r < 4; r++) s[nf][r] = 0.0f;

        #pragma unroll
        for (int ks = 0; ks < 8; ks++) {
            const int k0 = ks * 8;
            #pragma unroll
            for (int nf = 0; nf < 8; nf++) {
                uint32_t b[2];
                const float* bp = Ks + (nf * 8 + g) * KSTR + k0 + t;
                b[0] = __float_as_uint(bp[0]);
                b[1] = __float_as_uint(bp[4]);
                mma_tf32(s[nf], qf[ks], b);
            }
        }

        if (sb * 64 + 63 > qb * 128 + 16 * w) {
            #pragma unroll
            for (int nf = 0; nf < 8; nf++) {
                const int c0 = sb * 64 + nf * 8 + 2 * t;
                if (c0 > rowA)     s[nf][0] = -1e30f;
                if (c0 + 1 > rowA) s[nf][1] = -1e30f;
                if (c0 > rowA + 8)     s[nf][2] = -1e30f;
                if (c0 + 1 > rowA + 8) s[nf][3] = -1e30f;
            }
        }

        float mxA = -1e30f, mxB = -1e30f;
        #pragma unroll
        for (int nf = 0; nf < 8; nf++) {
            mxA = fmaxf(mxA, fmaxf(s[nf][0], s[nf][1]));
            mxB = fmaxf(mxB, fmaxf(s[nf][2], s[nf][3]));
        }
        mxA = fmaxf(mxA, __shfl_xor_sync(0xFFFFFFFF, mxA, 1));
        mxA = fmaxf(mxA, __shfl_xor_sync(0xFFFFFFFF, mxA, 2));
        mxB = fmaxf(mxB, __shfl_xor_sync(0xFFFFFFFF, mxB, 1));
        mxB = fmaxf(mxB, __shfl_xor_sync(0xFFFFFFFF, mxB, 2));

        const float mnA = fmaxf(mA, mxA);
        const float mnB = fmaxf(mB, mxB);
        const float aA = __expf(mA - mnA);
        const float aB = __expf(mB - mnB);
        mA = mnA; mB = mnB;

        float suA = 0.0f, suB = 0.0f;
        #pragma unroll
        for (int nf = 0; nf < 8; nf++) {
            float p0 = __expf(s[nf][0] - mnA);
            float p1 = __expf(s[nf][1] - mnA);
            float p2 = __expf(s[nf][2] - mnB);
            float p3 = __expf(s[nf][3] - mnB);
            suA += p0 + p1; suB += p2 + p3;
            s[nf][0] = to_tf32(p0); s[nf][1] = to_tf32(p1);
            s[nf][2] = to_tf32(p2); s[nf][3] = to_tf32(p3);
        }
        suA += __shfl_xor_sync(0xFFFFFFFF, suA, 1);
        suA += __shfl_xor_sync(0xFFFFFFFF, suA, 2);
        suB += __shfl_xor_sync(0xFFFFFFFF, suB, 1);
        suB += __shfl_xor_sync(0xFFFFFFFF, suB, 2);
        lA = lA * aA + suA;
        lB = lB * aB + suB;

        #pragma unroll
        for (int nf = 0; nf < 8; nf++) {
            o[nf][0] *= aA; o[nf][1] *= aA;
            o[nf][2] *= aB; o[nf][3] *= aB;
        }

        #pragma unroll
        for (int nf = 0; nf < 8; nf++) {
            *(float2*)(Ps + (16 * w + g) * PSTR + nf * 8 + 2 * t) =
                make_float2(s[nf][0], s[nf][1]);
            *(float2*)(Ps + (16 * w + g + 8) * PSTR + nf * 8 + 2 * t) =
                make_float2(s[nf][2], s[nf][3]);
        }
        __syncwarp();

        #pragma unroll
        for (int ks = 0; ks < 8; ks++) {
            const int k0 = ks * 8;
            uint32_t a[4];
            const float* ap = Ps + (16 * w + g) * PSTR + k0 + t;
            a[0] = __float_as_uint(ap[0]);
            a[1] = __float_as_uint(ap[8 * PSTR]);
            a[2] = __float_as_uint(ap[4]);
            a[3] = __float_as_uint(ap[8 * PSTR + 4]);
            #pragma unroll
            for (int nf = 0; nf < 8; nf++) {
                uint32_t b[2];
                b[0] = __float_as_uint(Vs[(k0 + t) * VSTR + nf * 8 + g]);
                b[1] = __float_as_uint(Vs[(k0 + t + 4) * VSTR + nf * 8 + g]);
                mma_tf32(o[nf], a, b);
            }
        }
    }

    const int b = bh >> 4, h = bh & 15;
    const float invA = 1.0f / lA;
    const float invB = 1.0f / lB;
    float* dstA = g_att + ((size_t)(b * T_ + rowA)) * C_ + h * D_;
    float* dstB = g_att + ((size_t)(b * T_ + rowA + 8)) * C_ + h * D_;
    #pragma unroll
    for (int nf = 0; nf < 8; nf++) {
        const int cc = nf * 8 + 2 * t;
        *(float2*)(dstA + cc) =
            make_float2(to_tf32(o[nf][0] * invA), to_tf32(o[nf][1] * invA));
        *(float2*)(dstB + cc) =
            make_float2(to_tf32(o[nf][2] * invB), to_tf32(o[nf][3] * invB));
    }
}

// ===========================================================================
extern "C" void kernel_launch(void* const* d_in, const int* in_sizes, int n_in,
                              void* d_out, int out_size)
{
    const float* x  = (const float*)d_in[0];
    const float* Wq = (const float*)d_in[1];
    const float* Wk = (const float*)d_in[2];
    const float* Wv = (const float*)d_in[3];
    const float* Wo = (const float*)d_in[4];
    const float* bo = (const float*)d_in[5];
    float* out = (float*)d_out;

    cudaFuncSetAttribute(attn_mma_kernel, cudaFuncAttributeMaxDynamicSharedMemorySize,
                         ATTN_SMEM_BYTES);
    cudaFuncSetAttribute(qkv_tc, cudaFuncAttributeMaxDynamicSharedMemorySize,
                         GEMM_SMEM_BYTES);
    cudaFuncSetAttribute(proj_tc, cudaFuncAttributeMaxDynamicSharedMemorySize,
                         GEMM_SMEM_BYTES);

    round_x<<<BT_ * C_ / (256 * 4), 256>>>(x);
    transpose_qkv_w<<<dim3(32, 2, 48), 256>>>(Wq, Wk, Wv);
    transpose_wo<<<dim3(32, 32), 256>>>(Wo);
    qkv_tc<<<dim3(64, 24), 128, GEMM_SMEM_BYTES>>>();
    attn_mma_kernel<<<dim3(T_ / 128, B_ * H_), 256, ATTN_SMEM_BYTES>>>();
    proj_tc<<<dim3(64, 8), 128, GEMM_SMEM_BYTES>>>(out, bo);
}